// round 14
// baseline (speedup 1.0000x reference)
#include <cuda_runtime.h>
#include <cuda_bf16.h>
#include <cstdint>

#define NN 20000
#define NE 320000
#define HID 256
#define NQKV 768
#define NHEADS 8
#define MB_TOT 1256          // 157*8 row-blocks of 16 (padded)
#define MAXE 96              // smem-cached edges per row (Poisson(16): overflow ~0)

// ---------------- scratch (static device globals; no allocation) -------------
__device__ float g_af [(size_t)MB_TOT * 32 * 128];  // A fragments (tf32 h)
__device__ float g_of [(size_t)MB_TOT * 32 * 128];  // attention-out fragments
__device__ float g_wf [262144];                     // Wqkv frags + Wo frags
__device__ float g_bias[NQKV];                      // concat bq|bk|bv
__device__ float g_qkv[(size_t)NN * NQKV];          // q|k|v rows
__device__ float g_s  [(size_t)NE * NHEADS];        // overflow score spill
__device__ int   g_deg[NN];
__device__ int   g_off[NN + 1];
__device__ int   g_fill[NN];
__device__ int   g_perm[NE];

// ---------------- helpers ----------------------------------------------------
__device__ __forceinline__ uint32_t smem_u32(const void* p) {
    uint32_t a;
    asm("{ .reg .u64 t; cvta.to.shared.u64 t, %1; cvt.u32.u64 %0, t; }" : "=r"(a) : "l"(p));
    return a;
}
__device__ __forceinline__ float f2tf32(float a) {
    uint32_t u; asm("cvt.rna.tf32.f32 %0, %1;" : "=r"(u) : "f"(a));
    return __uint_as_float(u);
}
__device__ __forceinline__ size_t frag_a_idx(int row, int c) {
    return ((size_t)(row >> 4) * 32 + (c >> 3)) * 128 +
           ((row & 7) * 4 + (c & 3)) * 4 + ((row >> 3) & 1) + 2 * ((c >> 2) & 1);
}
__device__ __forceinline__ size_t frag_b_idx(int k, int n) {
    return ((size_t)(n >> 3) * 32 + (k >> 3)) * 64 +
           ((n & 7) * 4 + (k & 3)) * 2 + ((k >> 2) & 1);
}
__device__ __forceinline__ void cp_async16(uint32_t dst, const float* src) {
    asm volatile("cp.async.cg.shared.global [%0], [%1], 16;" :: "r"(dst), "l"(src) : "memory");
}
__device__ __forceinline__ void mma1688(float* d, const float4& a, const float2& b) {
    asm volatile(
        "mma.sync.aligned.m16n8k8.row.col.f32.tf32.tf32.f32 "
        "{%0,%1,%2,%3}, {%4,%5,%6,%7}, {%8,%9}, {%0,%1,%2,%3};"
        : "+f"(d[0]), "+f"(d[1]), "+f"(d[2]), "+f"(d[3])
        : "r"(__float_as_uint(a.x)), "r"(__float_as_uint(a.y)),
          "r"(__float_as_uint(a.z)), "r"(__float_as_uint(a.w)),
          "r"(__float_as_uint(b.x)), "r"(__float_as_uint(b.y)));
}

// ---------------- prep: tf32 round + fragment swizzle ------------------------
__global__ void prep_a(const float* __restrict__ h) {
    int i = blockIdx.x * blockDim.x + threadIdx.x;
    if (i >= NN * HID) return;
    int row = i >> 8, c = i & 255;
    g_af[frag_a_idx(row, c)] = f2tf32(h[i]);
}
__global__ void prep_wqkv(const float* __restrict__ Wq, const float* __restrict__ Wk,
                          const float* __restrict__ Wv, const float* __restrict__ bq,
                          const float* __restrict__ bk, const float* __restrict__ bv) {
    int i = blockIdx.x * blockDim.x + threadIdx.x;
    if (i < NQKV)
        g_bias[i] = (i < 256) ? bq[i] : (i < 512) ? bk[i - 256] : bv[i - 512];
    if (i >= 3 * HID * HID) return;
    int which = i >> 16, rem = i & 65535;
    int k = rem >> 8, n = rem & 255;
    const float* W = (which == 0) ? Wq : (which == 1) ? Wk : Wv;
    g_wf[frag_b_idx(k, which * 256 + n)] = f2tf32(W[rem]);
}
__global__ void prep_wo(const float* __restrict__ Wo) {
    int i = blockIdx.x * blockDim.x + threadIdx.x;
    if (i >= HID * HID) return;
    int k = i >> 8, n = i & 255;
    g_wf[196608 + frag_b_idx(k, n)] = f2tf32(Wo[i]);
}

// ---------------- tf32 mma.sync GEMM: C = (A @ W + bias) * colscale ----------
// CTA 128(M) x 256(N), 16 warps (2x8), warp tile 64x32, K-chunk 32.
// A staged in SMEM (double-buffered cp.async, fragment layout).
// B fragments loaded DIRECTLY from L2 via LDG.64 with 1-step register prefetch.
#define SMEM_GEMM 32768

__device__ __forceinline__ void load_a_stage(
    uint32_t da, int c, const float* __restrict__ Af, int mb0, int tid)
{
    #pragma unroll
    for (int i = 0; i < 2; i++) {      // A: 1024 x 16B over 512 threads
        int idx = tid + i * 512;
        int tile = idx >> 5, l = idx & 31;         // tile = mbL*4 + kbL
        int mbL = tile >> 2, kbL = tile & 3;
        const float* src = Af + ((size_t)(mb0 + mbL) * 32 + c * 4 + kbL) * 128 + l * 4;
        cp_async16(da + idx * 16, src);
    }
    asm volatile("cp.async.commit_group;" ::: "memory");
}

__global__ void __launch_bounds__(512, 1) gemm_mma(
    const float* __restrict__ Af, const float* __restrict__ Bf,
    const float* __restrict__ bias, float* __restrict__ C, int M, int ldc,
    float scale, int scale_cols)
{
    extern __shared__ float sm[];
    float* sA[2] = { sm, sm + 4096 };

    int tid = threadIdx.x, wid = tid >> 5, lane = tid & 31;
    int wm = wid >> 3, wn = wid & 7;               // 2 x 8 warp grid
    int mb0 = blockIdx.x * 8;
    int nb0 = blockIdx.y * 32;

    float acc[4][4][4];
    #pragma unroll
    for (int a = 0; a < 4; a++)
        #pragma unroll
        for (int b = 0; b < 4; b++)
            #pragma unroll
            for (int r = 0; r < 4; r++) acc[a][b][r] = 0.f;

    uint32_t uA[2] = { smem_u32(sA[0]), smem_u32(sA[1]) };

    // B fragment base for this warp: 4 n-blocks (wn*4+ni), k-sub kb = c*4+s
    const float* bbase = Bf + ((size_t)(nb0 + wn * 4) * 32) * 64 + lane * 2;
    // tile (ni, kb) at offset (ni*32 + kb)*64

    load_a_stage(uA[0], 0, Af, mb0, tid);

    float2 bc[4], bn[4];
    #pragma unroll
    for (int ni = 0; ni < 4; ni++)
        bc[ni] = *(const float2*)(bbase + (ni * 32 + 0) * 64);

    #pragma unroll
    for (int c = 0; c < 8; c++) {
        if (c < 7) {
            load_a_stage(uA[(c + 1) & 1], c + 1, Af, mb0, tid);
            asm volatile("cp.async.wait_group 1;" ::: "memory");
        } else {
            asm volatile("cp.async.wait_group 0;" ::: "memory");
        }
        __syncthreads();
        const float* cA = sA[c & 1];
        #pragma unroll
        for (int s = 0; s < 4; s++) {
            int t = c * 4 + s;
            // prefetch next step's B frags from L2
            if (t < 31) {
                int kb = t + 1;
                #pragma unroll
                for (int ni = 0; ni < 4; ni++)
                    bn[ni] = *(const float2*)(bbase + (ni * 32 + kb) * 64);
            }
            float4 a[4];
            #pragma unroll
            for (int mi = 0; mi < 4; mi++)
                a[mi] = *(const float4*)(cA + ((wm * 4 + mi) * 4 + s) * 128 + lane * 4);
            #pragma unroll
            for (int mi = 0; mi < 4; mi++)
                #pragma unroll
                for (int ni = 0; ni < 4; ni++)
                    mma1688(acc[mi][ni], a[mi], bc[ni]);
            #pragma unroll
            for (int ni = 0; ni < 4; ni++) bc[ni] = bn[ni];
        }
        __syncthreads();
    }

    // epilogue
    int rbase = blockIdx.x * 128 + wm * 64 + (lane >> 2);
    int cbase = nb0 * 8 + wn * 32 + (lane & 3) * 2;
    #pragma unroll
    for (int mi = 0; mi < 4; mi++) {
        #pragma unroll
        for (int half = 0; half < 2; half++) {
            int row = rbase + mi * 16 + half * 8;
            if (row < M) {
                #pragma unroll
                for (int ni = 0; ni < 4; ni++) {
                    int col = cbase + ni * 8;
                    float sc = (col < scale_cols) ? scale : 1.f;
                    float2 o;
                    o.x = (acc[mi][ni][half * 2 + 0] + bias[col])     * sc;
                    o.y = (acc[mi][ni][half * 2 + 1] + bias[col + 1]) * sc;
                    *(float2*)(C + (size_t)row * ldc + col) = o;
                }
            }
        }
    }
}

// ---------------- CSR build ---------------------------------------------------
__global__ void count_deg(const int* __restrict__ rows) {
    int i = blockIdx.x * blockDim.x + threadIdx.x;
    if (i < NE) atomicAdd(&g_deg[rows[i]], 1);
}
__global__ __launch_bounds__(1024) void scan_deg() {
    __shared__ int warp_sums[32];
    __shared__ int carry;
    int tid = threadIdx.x;
    int lane = tid & 31, w = tid >> 5;
    if (tid == 0) carry = 0;
    __syncthreads();
    for (int base = 0; base < NN; base += 1024) {
        int i = base + tid;
        int v = (i < NN) ? g_deg[i] : 0;
        int x = v;
        #pragma unroll
        for (int d = 1; d < 32; d <<= 1) {
            int y = __shfl_up_sync(0xffffffffu, x, d);
            if (lane >= d) x += y;
        }
        if (lane == 31) warp_sums[w] = x;
        __syncthreads();
        if (w == 0) {
            int s = warp_sums[lane];
            #pragma unroll
            for (int d = 1; d < 32; d <<= 1) {
                int y = __shfl_up_sync(0xffffffffu, s, d);
                if (lane >= d) s += y;
            }
            warp_sums[lane] = s;
        }
        __syncthreads();
        int excl = x - v + carry + (w ? warp_sums[w - 1] : 0);
        if (i < NN) g_off[i] = excl;
        int blocktotal = warp_sums[31];
        __syncthreads();
        if (tid == 0) carry += blocktotal;
        __syncthreads();
    }
    if (tid == 0) g_off[NN] = carry;
}
__global__ void scatter_edges(const int* __restrict__ rows) {
    int i = blockIdx.x * blockDim.x + threadIdx.x;
    if (i < NE) {
        int r = rows[i];
        int pos = g_off[r] + atomicAdd(&g_fill[r], 1);
        g_perm[pos] = i;
    }
}
// deterministic per-row order; sort in registers (L1) not global RMW chains
__global__ void sort_perm() {
    int r = blockIdx.x * blockDim.x + threadIdx.x;
    if (r >= NN) return;
    int b = g_off[r], e = g_off[r + 1];
    int n = e - b;
    if (n <= 1) return;
    if (n <= MAXE) {
        int loc[MAXE];
        for (int i = 0; i < n; i++) loc[i] = g_perm[b + i];
        for (int i = 1; i < n; i++) {
            int key = loc[i], j = i - 1;
            while (j >= 0 && loc[j] > key) { loc[j + 1] = loc[j]; j--; }
            loc[j + 1] = key;
        }
        for (int i = 0; i < n; i++) g_perm[b + i] = loc[i];
    } else {
        for (int i = b + 1; i < e; i++) {
            int key = g_perm[i], j = i - 1;
            while (j >= b && g_perm[j] > key) { g_perm[j + 1] = g_perm[j]; j--; }
            g_perm[j + 1] = key;
        }
    }
}

// ------ fused SDDMM + softmax + SPMM: one warp per row -----------------------
__global__ __launch_bounds__(256) void edge_fused(const int* __restrict__ cols)
{
    __shared__ float sp[8][MAXE][8];   // [warp][edge][head] scores -> probs
    int w = threadIdx.x >> 5, lane = threadIdx.x & 31;
    int row = blockIdx.x * 8 + w;
    if (row >= NN) return;
    int beg = g_off[row], deg = g_off[row + 1] - beg;
    int hh = lane & 7, sub = lane >> 3;

    const float* qrp = g_qkv + (size_t)row * NQKV;
    float qr[8];
    #pragma unroll
    for (int j = 0; j < 8; j++) qr[j] = qrp[lane + 32 * j];

    // phase 1: scores
    for (int t = 0; t < deg; t++) {
        int e = g_perm[beg + t];
        int c = __ldg(&cols[e]);
        const float* kr = g_qkv + (size_t)c * NQKV + 256;
        float acc = 0.f;
        #pragma unroll
        for (int j = 0; j < 8; j++) acc += qr[j] * kr[lane + 32 * j];
        acc += __shfl_xor_sync(0xffffffffu, acc, 8);
        acc += __shfl_xor_sync(0xffffffffu, acc, 16);
        if (lane < 8) {
            if (t < MAXE) sp[w][t][lane] = acc;
            else          g_s[(size_t)e * 8 + lane] = acc;
        }
    }
    __syncwarp();

    float m = -1e30f;
    for (int t = sub; t < deg; t += 4) {
        float s = (t < MAXE) ? sp[w][t][hh] : g_s[(size_t)g_perm[beg + t] * 8 + hh];
        m = fmaxf(m, s);
    }
    m = fmaxf(m, __shfl_xor_sync(0xffffffffu, m, 8));
    m = fmaxf(m, __shfl_xor_sync(0xffffffffu, m, 16));
    float z = 0.f;
    for (int t = sub; t < deg; t += 4) {
        float s = (t < MAXE) ? sp[w][t][hh] : g_s[(size_t)g_perm[beg + t] * 8 + hh];
        z += __expf(s - m);
    }
    z += __shfl_xor_sync(0xffffffffu, z, 8);
    z += __shfl_xor_sync(0xffffffffu, z, 16);
    float invz = deg ? (1.f / z) : 0.f;
    __syncwarp();

    for (int t = sub; t < deg && t < MAXE; t += 4)
        sp[w][t][hh] = __expf(sp[w][t][hh] - m) * invz;
    __syncwarp();

    // phase 2: SPMM
    float acc[8];
    #pragma unroll
    for (int j = 0; j < 8; j++) acc[j] = 0.f;
    for (int t = 0; t < deg; t++) {
        int e = g_perm[beg + t];
        int c = __ldg(&cols[e]);
        float p = (t < MAXE) ? sp[w][t][hh]
                             : __expf(g_s[(size_t)e * 8 + hh] - m) * invz;
        const float* vr = g_qkv + (size_t)c * NQKV + 512;
        #pragma unroll
        for (int j = 0; j < 8; j++) acc[j] += p * vr[lane + 32 * j];
    }
    #pragma unroll
    for (int j = 0; j < 8; j++)
        g_of[frag_a_idx(row, lane + 32 * j)] = f2tf32(acc[j]);
}

// ---------------- launch -----------------------------------------------------
extern "C" void kernel_launch(void* const* d_in, const int* in_sizes, int n_in,
                              void* d_out, int out_size)
{
    const float* h  = (const float*)d_in[0];
    const float* Wq = (const float*)d_in[1];
    const float* bq = (const float*)d_in[2];
    const float* Wk = (const float*)d_in[3];
    const float* bk = (const float*)d_in[4];
    const float* Wv = (const float*)d_in[5];
    const float* bv = (const float*)d_in[6];
    const float* Wo = (const float*)d_in[7];
    const float* bo = (const float*)d_in[8];
    const int* rows = (const int*)d_in[9];
    const int* cols = (const int*)d_in[10];
    float* out = (float*)d_out;

    void *paf, *pof, *pwf, *pbias, *pqkv, *pdeg, *pfill;
    cudaGetSymbolAddress(&paf, g_af);
    cudaGetSymbolAddress(&pof, g_of);
    cudaGetSymbolAddress(&pwf, g_wf);
    cudaGetSymbolAddress(&pbias, g_bias);
    cudaGetSymbolAddress(&pqkv, g_qkv);
    cudaGetSymbolAddress(&pdeg, g_deg);
    cudaGetSymbolAddress(&pfill, g_fill);
    float* wf = (float*)pwf;

    cudaFuncSetAttribute(gemm_mma, cudaFuncAttributeMaxDynamicSharedMemorySize, SMEM_GEMM);

    const float scaling = 0.17677669529663687f;  // 32^-0.5

    cudaMemsetAsync(pdeg, 0, NN * sizeof(int));
    cudaMemsetAsync(pfill, 0, NN * sizeof(int));

    // 1-3: prep
    prep_a<<<(NN * HID + 255) / 256, 256>>>(h);
    prep_wqkv<<<(3 * HID * HID + 255) / 256, 256>>>(Wq, Wk, Wv, bq, bk, bv);
    prep_wo<<<(HID * HID + 255) / 256, 256>>>(Wo);

    // 4: fused QKV GEMM (slot 4 for ncu)
    dim3 gQ((NN + 127) / 128, 3);
    gemm_mma<<<gQ, 512, SMEM_GEMM>>>((const float*)paf, wf, (const float*)pbias,
                                     (float*)pqkv, NN, NQKV, scaling, 256);

    // 5-8: CSR build
    count_deg<<<(NE + 255) / 256, 256>>>(rows);
    scan_deg<<<1, 1024>>>();
    scatter_edges<<<(NE + 255) / 256, 256>>>(rows);
    sort_perm<<<(NN + 255) / 256, 256>>>();

    // 9: fused edge phase
    edge_fused<<<(NN + 7) / 8, 256>>>(cols);

    // 10: output GEMM
    dim3 gO((NN + 127) / 128, 1);
    gemm_mma<<<gO, 512, SMEM_GEMM>>>((const float*)pof, wf + 196608, bo,
                                     out, NN, HID, 1.f, 0);
}

// round 15
// speedup vs baseline: 1.0211x; 1.0211x over previous
#include <cuda_runtime.h>
#include <cuda_bf16.h>
#include <cstdint>

#define NN 20000
#define NE 320000
#define HID 256
#define NQKV 768
#define NHEADS 8
#define MB_TOT 1256          // 157*8 row-blocks of 16 (padded)
#define MAXE 96              // smem-cached edges per row (Poisson(16): overflow ~0)

// ---------------- scratch (static device globals; no allocation) -------------
__device__ float g_af [(size_t)MB_TOT * 32 * 128];  // A fragments (tf32 h)
__device__ float g_of [(size_t)MB_TOT * 32 * 128];  // attention-out fragments
__device__ float g_wf [262144];                     // Wqkv frags + Wo frags
__device__ float g_bias[NQKV];                      // concat bq|bk|bv
__device__ float g_qkv[(size_t)NN * NQKV];          // q|k|v rows
__device__ float g_s  [(size_t)NE * NHEADS];        // overflow score spill
__device__ int   g_deg[NN];
__device__ int   g_off[NN + 1];
__device__ int   g_fill[NN];
__device__ int   g_perm[NE];

// ---------------- helpers ----------------------------------------------------
__device__ __forceinline__ uint32_t smem_u32(const void* p) {
    uint32_t a;
    asm("{ .reg .u64 t; cvta.to.shared.u64 t, %1; cvt.u32.u64 %0, t; }" : "=r"(a) : "l"(p));
    return a;
}
__device__ __forceinline__ float f2tf32(float a) {
    uint32_t u; asm("cvt.rna.tf32.f32 %0, %1;" : "=r"(u) : "f"(a));
    return __uint_as_float(u);
}
__device__ __forceinline__ size_t frag_a_idx(int row, int c) {
    return ((size_t)(row >> 4) * 32 + (c >> 3)) * 128 +
           ((row & 7) * 4 + (c & 3)) * 4 + ((row >> 3) & 1) + 2 * ((c >> 2) & 1);
}
__device__ __forceinline__ size_t frag_b_idx(int k, int n) {
    return ((size_t)(n >> 3) * 32 + (k >> 3)) * 64 +
           ((n & 7) * 4 + (k & 3)) * 2 + ((k >> 2) & 1);
}
__device__ __forceinline__ void cp_async16(uint32_t dst, const float* src) {
    asm volatile("cp.async.cg.shared.global [%0], [%1], 16;" :: "r"(dst), "l"(src) : "memory");
}
__device__ __forceinline__ void mma1688(float* d, const float4& a, const float2& b) {
    asm volatile(
        "mma.sync.aligned.m16n8k8.row.col.f32.tf32.tf32.f32 "
        "{%0,%1,%2,%3}, {%4,%5,%6,%7}, {%8,%9}, {%0,%1,%2,%3};"
        : "+f"(d[0]), "+f"(d[1]), "+f"(d[2]), "+f"(d[3])
        : "r"(__float_as_uint(a.x)), "r"(__float_as_uint(a.y)),
          "r"(__float_as_uint(a.z)), "r"(__float_as_uint(a.w)),
          "r"(__float_as_uint(b.x)), "r"(__float_as_uint(b.y)));
}

// ---------------- prep: tf32 round + fragment swizzle ------------------------
__global__ void prep_a(const float* __restrict__ h) {
    int i = blockIdx.x * blockDim.x + threadIdx.x;
    if (i >= NN * HID) return;
    int row = i >> 8, c = i & 255;
    g_af[frag_a_idx(row, c)] = f2tf32(h[i]);
}
__global__ void prep_wqkv(const float* __restrict__ Wq, const float* __restrict__ Wk,
                          const float* __restrict__ Wv, const float* __restrict__ bq,
                          const float* __restrict__ bk, const float* __restrict__ bv) {
    int i = blockIdx.x * blockDim.x + threadIdx.x;
    if (i < NQKV)
        g_bias[i] = (i < 256) ? bq[i] : (i < 512) ? bk[i - 256] : bv[i - 512];
    if (i >= 3 * HID * HID) return;
    int which = i >> 16, rem = i & 65535;
    int k = rem >> 8, n = rem & 255;
    const float* W = (which == 0) ? Wq : (which == 1) ? Wk : Wv;
    g_wf[frag_b_idx(k, which * 256 + n)] = f2tf32(W[rem]);
}
__global__ void prep_wo(const float* __restrict__ Wo) {
    int i = blockIdx.x * blockDim.x + threadIdx.x;
    if (i >= HID * HID) return;
    int k = i >> 8, n = i & 255;
    g_wf[196608 + frag_b_idx(k, n)] = f2tf32(Wo[i]);
}

// ---------------- tf32 mma.sync GEMM: C = (A @ W + bias) * colscale ----------
// CTA 128(M) x 256(N), 16 warps (2x8), warp tile 64x32, K-chunk 32.
// A (16KB) + B (32KB) both SMEM double-buffered via cp.async.
#define SMEM_GEMM 98304

__device__ __forceinline__ void load_stage(
    uint32_t da, uint32_t db, int c, const float* __restrict__ Af,
    const float* __restrict__ Bf, int mb0, int nb0, int tid)
{
    #pragma unroll
    for (int i = 0; i < 2; i++) {      // A: 1024 x 16B over 512 threads
        int idx = tid + i * 512;
        int mbL = idx >> 7, kbL = (idx >> 5) & 3, l = idx & 31;
        const float* src = Af + ((size_t)(mb0 + mbL) * 32 + c * 4 + kbL) * 128 + l * 4;
        cp_async16(da + idx * 16, src);
    }
    #pragma unroll
    for (int i = 0; i < 4; i++) {      // B: 2048 x 16B
        int idx = tid + i * 512;
        int nbL = idx >> 6, kbL = (idx >> 4) & 3, part = idx & 15;
        const float* src = Bf + ((size_t)(nb0 + nbL) * 32 + c * 4 + kbL) * 64 + part * 4;
        cp_async16(db + idx * 16, src);
    }
    asm volatile("cp.async.commit_group;" ::: "memory");
}

__global__ void __launch_bounds__(512, 1) gemm_mma(
    const float* __restrict__ Af, const float* __restrict__ Bf,
    const float* __restrict__ bias, float* __restrict__ C, int M, int ldc,
    float scale, int scale_cols)
{
    extern __shared__ float sm[];
    float* sA[2] = { sm,         sm + 4096 };
    float* sB[2] = { sm + 8192,  sm + 16384 };

    int tid = threadIdx.x, wid = tid >> 5, lane = tid & 31;
    int wm = wid >> 3, wn = wid & 7;               // 2 x 8 warp grid
    int mb0 = blockIdx.x * 8;
    int nb0 = blockIdx.y * 32;

    float acc[4][4][4];
    #pragma unroll
    for (int a = 0; a < 4; a++)
        #pragma unroll
        for (int b = 0; b < 4; b++)
            #pragma unroll
            for (int r = 0; r < 4; r++) acc[a][b][r] = 0.f;

    uint32_t uA[2] = { smem_u32(sA[0]), smem_u32(sA[1]) };
    uint32_t uB[2] = { smem_u32(sB[0]), smem_u32(sB[1]) };

    load_stage(uA[0], uB[0], 0, Af, Bf, mb0, nb0, tid);

    #pragma unroll
    for (int c = 0; c < 8; c++) {
        if (c < 7) {
            load_stage(uA[(c + 1) & 1], uB[(c + 1) & 1], c + 1, Af, Bf, mb0, nb0, tid);
            asm volatile("cp.async.wait_group 1;" ::: "memory");
        } else {
            asm volatile("cp.async.wait_group 0;" ::: "memory");
        }
        __syncthreads();
        const float* cA = sA[c & 1];
        const float* cB = sB[c & 1];
        #pragma unroll
        for (int s = 0; s < 4; s++) {
            float4 a[4];
            float2 b[4];
            #pragma unroll
            for (int mi = 0; mi < 4; mi++)
                a[mi] = *(const float4*)(cA + ((wm * 4 + mi) * 4 + s) * 128 + lane * 4);
            #pragma unroll
            for (int ni = 0; ni < 4; ni++)
                b[ni] = *(const float2*)(cB + ((wn * 4 + ni) * 4 + s) * 64 + lane * 2);
            #pragma unroll
            for (int mi = 0; mi < 4; mi++)
                #pragma unroll
                for (int ni = 0; ni < 4; ni++)
                    mma1688(acc[mi][ni], a[mi], b[ni]);
        }
        __syncthreads();
    }

    // epilogue
    int rbase = blockIdx.x * 128 + wm * 64 + (lane >> 2);
    int cbase = nb0 * 8 + wn * 32 + (lane & 3) * 2;
    #pragma unroll
    for (int mi = 0; mi < 4; mi++) {
        #pragma unroll
        for (int half = 0; half < 2; half++) {
            int row = rbase + mi * 16 + half * 8;
            if (row < M) {
                #pragma unroll
                for (int ni = 0; ni < 4; ni++) {
                    int col = cbase + ni * 8;
                    float sc = (col < scale_cols) ? scale : 1.f;
                    float2 o;
                    o.x = (acc[mi][ni][half * 2 + 0] + bias[col])     * sc;
                    o.y = (acc[mi][ni][half * 2 + 1] + bias[col + 1]) * sc;
                    *(float2*)(C + (size_t)row * ldc + col) = o;
                }
            }
        }
    }
}

// ---------------- CSR build ---------------------------------------------------
__global__ void count_deg(const int* __restrict__ rows) {
    int i = blockIdx.x * blockDim.x + threadIdx.x;
    if (i < NE) atomicAdd(&g_deg[rows[i]], 1);
}
__global__ __launch_bounds__(1024) void scan_deg() {
    __shared__ int warp_sums[32];
    __shared__ int carry;
    int tid = threadIdx.x;
    int lane = tid & 31, w = tid >> 5;
    if (tid == 0) carry = 0;
    __syncthreads();
    for (int base = 0; base < NN; base += 1024) {
        int i = base + tid;
        int v = (i < NN) ? g_deg[i] : 0;
        int x = v;
        #pragma unroll
        for (int d = 1; d < 32; d <<= 1) {
            int y = __shfl_up_sync(0xffffffffu, x, d);
            if (lane >= d) x += y;
        }
        if (lane == 31) warp_sums[w] = x;
        __syncthreads();
        if (w == 0) {
            int s = warp_sums[lane];
            #pragma unroll
            for (int d = 1; d < 32; d <<= 1) {
                int y = __shfl_up_sync(0xffffffffu, s, d);
                if (lane >= d) s += y;
            }
            warp_sums[lane] = s;
        }
        __syncthreads();
        int excl = x - v + carry + (w ? warp_sums[w - 1] : 0);
        if (i < NN) g_off[i] = excl;
        int blocktotal = warp_sums[31];
        __syncthreads();
        if (tid == 0) carry += blocktotal;
        __syncthreads();
    }
    if (tid == 0) g_off[NN] = carry;
}
__global__ void scatter_edges(const int* __restrict__ rows) {
    int i = blockIdx.x * blockDim.x + threadIdx.x;
    if (i < NE) {
        int r = rows[i];
        int pos = g_off[r] + atomicAdd(&g_fill[r], 1);
        g_perm[pos] = i;
    }
}
// deterministic per-row order; sort in registers (L1) not global RMW chains
__global__ void sort_perm() {
    int r = blockIdx.x * blockDim.x + threadIdx.x;
    if (r >= NN) return;
    int b = g_off[r], e = g_off[r + 1];
    int n = e - b;
    if (n <= 1) return;
    if (n <= MAXE) {
        int loc[MAXE];
        for (int i = 0; i < n; i++) loc[i] = g_perm[b + i];
        for (int i = 1; i < n; i++) {
            int key = loc[i], j = i - 1;
            while (j >= 0 && loc[j] > key) { loc[j + 1] = loc[j]; j--; }
            loc[j + 1] = key;
        }
        for (int i = 0; i < n; i++) g_perm[b + i] = loc[i];
    } else {
        for (int i = b + 1; i < e; i++) {
            int key = g_perm[i], j = i - 1;
            while (j >= b && g_perm[j] > key) { g_perm[j + 1] = g_perm[j]; j--; }
            g_perm[j + 1] = key;
        }
    }
}

// ------ fused SDDMM + softmax + SPMM: one warp per row -----------------------
__global__ __launch_bounds__(256) void edge_fused(const int* __restrict__ cols)
{
    __shared__ float sp[8][MAXE][8];   // [warp][edge][head] scores -> probs
    int w = threadIdx.x >> 5, lane = threadIdx.x & 31;
    int row = blockIdx.x * 8 + w;
    if (row >= NN) return;
    int beg = g_off[row], deg = g_off[row + 1] - beg;
    int hh = lane & 7, sub = lane >> 3;

    const float* qrp = g_qkv + (size_t)row * NQKV;
    float qr[8];
    #pragma unroll
    for (int j = 0; j < 8; j++) qr[j] = qrp[lane + 32 * j];

    // phase 1: scores
    for (int t = 0; t < deg; t++) {
        int e = g_perm[beg + t];
        int c = __ldg(&cols[e]);
        const float* kr = g_qkv + (size_t)c * NQKV + 256;
        float acc = 0.f;
        #pragma unroll
        for (int j = 0; j < 8; j++) acc += qr[j] * kr[lane + 32 * j];
        acc += __shfl_xor_sync(0xffffffffu, acc, 8);
        acc += __shfl_xor_sync(0xffffffffu, acc, 16);
        if (lane < 8) {
            if (t < MAXE) sp[w][t][lane] = acc;
            else          g_s[(size_t)e * 8 + lane] = acc;
        }
    }
    __syncwarp();

    float m = -1e30f;
    for (int t = sub; t < deg; t += 4) {
        float s = (t < MAXE) ? sp[w][t][hh] : g_s[(size_t)g_perm[beg + t] * 8 + hh];
        m = fmaxf(m, s);
    }
    m = fmaxf(m, __shfl_xor_sync(0xffffffffu, m, 8));
    m = fmaxf(m, __shfl_xor_sync(0xffffffffu, m, 16));
    float z = 0.f;
    for (int t = sub; t < deg; t += 4) {
        float s = (t < MAXE) ? sp[w][t][hh] : g_s[(size_t)g_perm[beg + t] * 8 + hh];
        z += __expf(s - m);
    }
    z += __shfl_xor_sync(0xffffffffu, z, 8);
    z += __shfl_xor_sync(0xffffffffu, z, 16);
    float invz = deg ? (1.f / z) : 0.f;
    __syncwarp();

    for (int t = sub; t < deg && t < MAXE; t += 4)
        sp[w][t][hh] = __expf(sp[w][t][hh] - m) * invz;
    __syncwarp();

    // phase 2: SPMM
    float acc[8];
    #pragma unroll
    for (int j = 0; j < 8; j++) acc[j] = 0.f;
    for (int t = 0; t < deg; t++) {
        int e = g_perm[beg + t];
        int c = __ldg(&cols[e]);
        float p = (t < MAXE) ? sp[w][t][hh]
                             : __expf(g_s[(size_t)e * 8 + hh] - m) * invz;
        const float* vr = g_qkv + (size_t)c * NQKV + 512;
        #pragma unroll
        for (int j = 0; j < 8; j++) acc[j] += p * vr[lane + 32 * j];
    }
    #pragma unroll
    for (int j = 0; j < 8; j++)
        g_of[frag_a_idx(row, lane + 32 * j)] = f2tf32(acc[j]);
}

// ---------------- launch -----------------------------------------------------
extern "C" void kernel_launch(void* const* d_in, const int* in_sizes, int n_in,
                              void* d_out, int out_size)
{
    const float* h  = (const float*)d_in[0];
    const float* Wq = (const float*)d_in[1];
    const float* bq = (const float*)d_in[2];
    const float* Wk = (const float*)d_in[3];
    const float* bk = (const float*)d_in[4];
    const float* Wv = (const float*)d_in[5];
    const float* bv = (const float*)d_in[6];
    const float* Wo = (const float*)d_in[7];
    const float* bo = (const float*)d_in[8];
    const int* rows = (const int*)d_in[9];
    const int* cols = (const int*)d_in[10];
    float* out = (float*)d_out;

    void *paf, *pof, *pwf, *pbias, *pqkv, *pdeg, *pfill;
    cudaGetSymbolAddress(&paf, g_af);
    cudaGetSymbolAddress(&pof, g_of);
    cudaGetSymbolAddress(&pwf, g_wf);
    cudaGetSymbolAddress(&pbias, g_bias);
    cudaGetSymbolAddress(&pqkv, g_qkv);
    cudaGetSymbolAddress(&pdeg, g_deg);
    cudaGetSymbolAddress(&pfill, g_fill);
    float* wf = (float*)pwf;

    cudaFuncSetAttribute(gemm_mma, cudaFuncAttributeMaxDynamicSharedMemorySize, SMEM_GEMM);

    const float scaling = 0.17677669529663687f;  // 32^-0.5

    cudaMemsetAsync(pdeg, 0, NN * sizeof(int));
    cudaMemsetAsync(pfill, 0, NN * sizeof(int));

    // 1-3: prep
    prep_a<<<(NN * HID + 255) / 256, 256>>>(h);
    prep_wqkv<<<(3 * HID * HID + 255) / 256, 256>>>(Wq, Wk, Wv, bq, bk, bv);
    prep_wo<<<(HID * HID + 255) / 256, 256>>>(Wo);

    // 4: fused QKV GEMM (slot 4 for ncu)
    dim3 gQ((NN + 127) / 128, 3);
    gemm_mma<<<gQ, 512, SMEM_GEMM>>>((const float*)paf, wf, (const float*)pbias,
                                     (float*)pqkv, NN, NQKV, scaling, 256);

    // 5-8: CSR build
    count_deg<<<(NE + 255) / 256, 256>>>(rows);
    scan_deg<<<1, 1024>>>();
    scatter_edges<<<(NE + 255) / 256, 256>>>(rows);
    sort_perm<<<(NN + 255) / 256, 256>>>();

    // 9: fused edge phase
    edge_fused<<<(NN + 7) / 8, 256>>>(cols);

    // 10: output GEMM
    dim3 gO((NN + 127) / 128, 1);
    gemm_mma<<<gO, 512, SMEM_GEMM>>>((const float*)pof, wf + 196608, bo,
                                     out, NN, HID, 1.f, 0);
}

// round 16
// speedup vs baseline: 1.1639x; 1.1399x over previous
#include <cuda_runtime.h>
#include <cuda_fp16.h>
#include <cstdint>

#define NN 20000
#define NE 320000
#define HID 256
#define NQKV 768
#define NHEADS 8
#define MB_TOT 1256          // 157*8 row-blocks of 16 (padded)
#define MAXE 96              // smem-cached edges per row (Poisson(16): overflow ~0)

// ---------------- scratch (static device globals; no allocation) -------------
__device__ __half g_af[(size_t)MB_TOT * 4096];  // A fragments (fp16 h), 16 k-tiles/rowblk
__device__ __half g_of[(size_t)MB_TOT * 4096];  // attention-out fragments (fp16)
__device__ __half g_wf[262144];                 // Wqkv frags [196608] + Wo frags [65536]
__device__ float  g_bias[NQKV];                 // concat bq|bk|bv
__device__ float  g_qkv[(size_t)NN * NQKV];     // q|k|v rows (fp32)
__device__ float  g_s  [(size_t)NE * NHEADS];   // overflow score spill
__device__ int    g_deg[NN];
__device__ int    g_off[NN + 1];
__device__ int    g_fill[NN];
__device__ int    g_perm[NE];

// ---------------- helpers ----------------------------------------------------
__device__ __forceinline__ uint32_t smem_u32(const void* p) {
    uint32_t a;
    asm("{ .reg .u64 t; cvta.to.shared.u64 t, %1; cvt.u32.u64 %0, t; }" : "=r"(a) : "l"(p));
    return a;
}
// fp16 m16n8k16 A fragment layout: 16x16 tile = 256 halves
// lane=(row%8)*4+((c%8)>>1), reg=((row>>3)&1)+2*((c>>3)&1), half=c&1
__device__ __forceinline__ size_t frag_a16_idx(int row, int c) {
    return ((size_t)(row >> 4) * 16 + (c >> 4)) * 256 +
           ((row & 7) * 4 + ((c & 7) >> 1)) * 8 +
           (((row >> 3) & 1) + 2 * ((c >> 3) & 1)) * 2 + (c & 1);
}
// fp16 m16n8k16 B fragment layout (from W[k][n], col-major op): 16k x 8n = 128 halves
// lane=(n%8)*4+((k%8)>>1), reg=(k>>3)&1, half=k&1
__device__ __forceinline__ size_t frag_b16_idx(int k, int n) {
    return ((size_t)(n >> 3) * 16 + (k >> 4)) * 128 +
           ((n & 7) * 4 + ((k & 7) >> 1)) * 4 + ((k >> 3) & 1) * 2 + (k & 1);
}
__device__ __forceinline__ void cp_async16(uint32_t dst, const void* src) {
    asm volatile("cp.async.cg.shared.global [%0], [%1], 16;" :: "r"(dst), "l"(src) : "memory");
}
__device__ __forceinline__ void mma16816(float* d, const uint32_t* a, const uint32_t* b) {
    asm volatile(
        "mma.sync.aligned.m16n8k16.row.col.f32.f16.f16.f32 "
        "{%0,%1,%2,%3}, {%4,%5,%6,%7}, {%8,%9}, {%0,%1,%2,%3};"
        : "+f"(d[0]), "+f"(d[1]), "+f"(d[2]), "+f"(d[3])
        : "r"(a[0]), "r"(a[1]), "r"(a[2]), "r"(a[3]), "r"(b[0]), "r"(b[1]));
}

// ---------------- prep: fp16 round + fragment swizzle ------------------------
__global__ void prep_a(const float* __restrict__ h) {
    int i = blockIdx.x * blockDim.x + threadIdx.x;
    if (i >= NN * HID) return;
    int row = i >> 8, c = i & 255;
    g_af[frag_a16_idx(row, c)] = __float2half_rn(h[i]);
}
__global__ void prep_wqkv(const float* __restrict__ Wq, const float* __restrict__ Wk,
                          const float* __restrict__ Wv, const float* __restrict__ bq,
                          const float* __restrict__ bk, const float* __restrict__ bv) {
    int i = blockIdx.x * blockDim.x + threadIdx.x;
    if (i < NQKV)
        g_bias[i] = (i < 256) ? bq[i] : (i < 512) ? bk[i - 256] : bv[i - 512];
    if (i >= 3 * HID * HID) return;
    int which = i >> 16, rem = i & 65535;
    int k = rem >> 8, n = rem & 255;
    const float* W = (which == 0) ? Wq : (which == 1) ? Wk : Wv;
    g_wf[frag_b16_idx(k, which * 256 + n)] = __float2half_rn(W[rem]);
}
__global__ void prep_wo(const float* __restrict__ Wo) {
    int i = blockIdx.x * blockDim.x + threadIdx.x;
    if (i >= HID * HID) return;
    int k = i >> 8, n = i & 255;
    g_wf[196608 + frag_b16_idx(k, n)] = __float2half_rn(Wo[i]);
}

// ---------------- fp16 mma.sync GEMM: C = (A @ W + bias) * colscale ----------
// CTA 128(M) x 256(N), 8 warps (2x4), warp tile 64x64, K-chunk 64, 4 chunks.
// A (16KB) + B (32KB) per stage, double-buffered cp.async. 96KB SMEM.
#define SMEM_GEMM 98304

__device__ __forceinline__ void load_stage(
    uint32_t da, uint32_t db, int c, const __half* __restrict__ Af,
    const __half* __restrict__ Bf, int mb0, int nb0, int tid)
{
    #pragma unroll
    for (int i = 0; i < 4; i++) {      // A: 1024 x 16B (16KB)
        int idx = tid + i * 256;
        int tile = idx >> 5, off = idx & 31;       // tile = mbL*4 + kbL (512B tiles)
        int mbL = tile >> 2, kbL = tile & 3;
        const __half* src = Af + ((size_t)(mb0 + mbL) * 16 + c * 4 + kbL) * 256 + off * 8;
        cp_async16(da + idx * 16, src);
    }
    #pragma unroll
    for (int i = 0; i < 8; i++) {      // B: 2048 x 16B (32KB)
        int idx = tid + i * 256;
        int tile = idx >> 4, off = idx & 15;       // tile = nbL*4 + kbL (256B tiles)
        int nbL = tile >> 2, kbL = tile & 3;
        const __half* src = Bf + ((size_t)(nb0 + nbL) * 16 + c * 4 + kbL) * 128 + off * 8;
        cp_async16(db + idx * 16, src);
    }
    asm volatile("cp.async.commit_group;" ::: "memory");
}

__global__ void __launch_bounds__(256, 1) gemm_mma(
    const __half* __restrict__ Af, const __half* __restrict__ Bf,
    const float* __restrict__ bias, float* __restrict__ C, int M, int ldc,
    float scale, int scale_cols)
{
    extern __shared__ __half smh[];
    __half* sA[2] = { smh,          smh + 8192 };
    __half* sB[2] = { smh + 16384,  smh + 32768 };

    int tid = threadIdx.x, wid = tid >> 5, lane = tid & 31;
    int wm = wid >> 2, wn = wid & 3;               // 2 x 4 warp grid
    int mb0 = blockIdx.x * 8;                      // 16-row blocks
    int nb0 = blockIdx.y * 32;                     // 8-col blocks

    float acc[4][8][4];
    #pragma unroll
    for (int a = 0; a < 4; a++)
        #pragma unroll
        for (int b = 0; b < 8; b++)
            #pragma unroll
            for (int r = 0; r < 4; r++) acc[a][b][r] = 0.f;

    uint32_t uA[2] = { smem_u32(sA[0]), smem_u32(sA[1]) };
    uint32_t uB[2] = { smem_u32(sB[0]), smem_u32(sB[1]) };

    load_stage(uA[0], uB[0], 0, Af, Bf, mb0, nb0, tid);

    #pragma unroll
    for (int c = 0; c < 4; c++) {
        if (c < 3) {
            load_stage(uA[(c + 1) & 1], uB[(c + 1) & 1], c + 1, Af, Bf, mb0, nb0, tid);
            asm volatile("cp.async.wait_group 1;" ::: "memory");
        } else {
            asm volatile("cp.async.wait_group 0;" ::: "memory");
        }
        __syncthreads();
        const __half* cA = sA[c & 1];
        const __half* cB = sB[c & 1];
        #pragma unroll
        for (int s = 0; s < 4; s++) {              // 4 k16-steps per chunk
            uint32_t a[4][4], b[8][2];
            #pragma unroll
            for (int mi = 0; mi < 4; mi++) {
                const uint32_t* p = (const uint32_t*)(cA + ((wm * 4 + mi) * 4 + s) * 256 + lane * 8);
                a[mi][0] = p[0]; a[mi][1] = p[1]; a[mi][2] = p[2]; a[mi][3] = p[3];
            }
            #pragma unroll
            for (int ni = 0; ni < 8; ni++) {
                const uint32_t* p = (const uint32_t*)(cB + ((wn * 8 + ni) * 4 + s) * 128 + lane * 4);
                b[ni][0] = p[0]; b[ni][1] = p[1];
            }
            #pragma unroll
            for (int mi = 0; mi < 4; mi++)
                #pragma unroll
                for (int ni = 0; ni < 8; ni++)
                    mma16816(acc[mi][ni], a[mi], b[ni]);
        }
        __syncthreads();
    }

    // epilogue
    int rbase = blockIdx.x * 128 + wm * 64 + (lane >> 2);
    int cbase = nb0 * 8 + wn * 64 + (lane & 3) * 2;
    #pragma unroll
    for (int mi = 0; mi < 4; mi++) {
        #pragma unroll
        for (int half = 0; half < 2; half++) {
            int row = rbase + mi * 16 + half * 8;
            if (row < M) {
                #pragma unroll
                for (int ni = 0; ni < 8; ni++) {
                    int col = cbase + ni * 8;
                    float sc = (col < scale_cols) ? scale : 1.f;
                    float2 o;
                    o.x = (acc[mi][ni][half * 2 + 0] + bias[col])     * sc;
                    o.y = (acc[mi][ni][half * 2 + 1] + bias[col + 1]) * sc;
                    *(float2*)(C + (size_t)row * ldc + col) = o;
                }
            }
        }
    }
}

// ---------------- CSR build ---------------------------------------------------
__global__ void count_deg(const int* __restrict__ rows) {
    int i = blockIdx.x * blockDim.x + threadIdx.x;
    if (i < NE) atomicAdd(&g_deg[rows[i]], 1);
}
__global__ __launch_bounds__(1024) void scan_deg() {
    __shared__ int warp_sums[32];
    __shared__ int carry;
    int tid = threadIdx.x;
    int lane = tid & 31, w = tid >> 5;
    if (tid == 0) carry = 0;
    __syncthreads();
    for (int base = 0; base < NN; base += 1024) {
        int i = base + tid;
        int v = (i < NN) ? g_deg[i] : 0;
        int x = v;
        #pragma unroll
        for (int d = 1; d < 32; d <<= 1) {
            int y = __shfl_up_sync(0xffffffffu, x, d);
            if (lane >= d) x += y;
        }
        if (lane == 31) warp_sums[w] = x;
        __syncthreads();
        if (w == 0) {
            int s = warp_sums[lane];
            #pragma unroll
            for (int d = 1; d < 32; d <<= 1) {
                int y = __shfl_up_sync(0xffffffffu, s, d);
                if (lane >= d) s += y;
            }
            warp_sums[lane] = s;
        }
        __syncthreads();
        int excl = x - v + carry + (w ? warp_sums[w - 1] : 0);
        if (i < NN) g_off[i] = excl;
        int blocktotal = warp_sums[31];
        __syncthreads();
        if (tid == 0) carry += blocktotal;
        __syncthreads();
    }
    if (tid == 0) g_off[NN] = carry;
}
__global__ void scatter_edges(const int* __restrict__ rows) {
    int i = blockIdx.x * blockDim.x + threadIdx.x;
    if (i < NE) {
        int r = rows[i];
        int pos = g_off[r] + atomicAdd(&g_fill[r], 1);
        g_perm[pos] = i;
    }
}
// deterministic per-row order; sort in registers (L1) not global RMW chains
__global__ void sort_perm() {
    int r = blockIdx.x * blockDim.x + threadIdx.x;
    if (r >= NN) return;
    int b = g_off[r], e = g_off[r + 1];
    int n = e - b;
    if (n <= 1) return;
    if (n <= MAXE) {
        int loc[MAXE];
        for (int i = 0; i < n; i++) loc[i] = g_perm[b + i];
        for (int i = 1; i < n; i++) {
            int key = loc[i], j = i - 1;
            while (j >= 0 && loc[j] > key) { loc[j + 1] = loc[j]; j--; }
            loc[j + 1] = key;
        }
        for (int i = 0; i < n; i++) g_perm[b + i] = loc[i];
    } else {
        for (int i = b + 1; i < e; i++) {
            int key = g_perm[i], j = i - 1;
            while (j >= b && g_perm[j] > key) { g_perm[j + 1] = g_perm[j]; j--; }
            g_perm[j + 1] = key;
        }
    }
}

// ------ fused SDDMM + softmax + SPMM: one warp per row -----------------------
__global__ __launch_bounds__(256) void edge_fused(const int* __restrict__ cols)
{
    __shared__ float sp[8][MAXE][8];   // [warp][edge][head] scores -> probs
    int w = threadIdx.x >> 5, lane = threadIdx.x & 31;
    int row = blockIdx.x * 8 + w;
    if (row >= NN) return;
    int beg = g_off[row], deg = g_off[row + 1] - beg;
    int hh = lane & 7, sub = lane >> 3;

    const float* qrp = g_qkv + (size_t)row * NQKV;
    float qr[8];
    #pragma unroll
    for (int j = 0; j < 8; j++) qr[j] = qrp[lane + 32 * j];

    // phase 1: scores
    for (int t = 0; t < deg; t++) {
        int e = g_perm[beg + t];
        int c = __ldg(&cols[e]);
        const float* kr = g_qkv + (size_t)c * NQKV + 256;
        float acc = 0.f;
        #pragma unroll
        for (int j = 0; j < 8; j++) acc += qr[j] * kr[lane + 32 * j];
        acc += __shfl_xor_sync(0xffffffffu, acc, 8);
        acc += __shfl_xor_sync(0xffffffffu, acc, 16);
        if (lane < 8) {
            if (t < MAXE) sp[w][t][lane] = acc;
            else          g_s[(size_t)e * 8 + lane] = acc;
        }
    }
    __syncwarp();

    float m = -1e30f;
    for (int t = sub; t < deg; t += 4) {
        float s = (t < MAXE) ? sp[w][t][hh] : g_s[(size_t)g_perm[beg + t] * 8 + hh];
        m = fmaxf(m, s);
    }
    m = fmaxf(m, __shfl_xor_sync(0xffffffffu, m, 8));
    m = fmaxf(m, __shfl_xor_sync(0xffffffffu, m, 16));
    float z = 0.f;
    for (int t = sub; t < deg; t += 4) {
        float s = (t < MAXE) ? sp[w][t][hh] : g_s[(size_t)g_perm[beg + t] * 8 + hh];
        z += __expf(s - m);
    }
    z += __shfl_xor_sync(0xffffffffu, z, 8);
    z += __shfl_xor_sync(0xffffffffu, z, 16);
    float invz = deg ? (1.f / z) : 0.f;
    __syncwarp();

    for (int t = sub; t < deg && t < MAXE; t += 4)
        sp[w][t][hh] = __expf(sp[w][t][hh] - m) * invz;
    __syncwarp();

    // phase 2: SPMM
    float acc[8];
    #pragma unroll
    for (int j = 0; j < 8; j++) acc[j] = 0.f;
    for (int t = 0; t < deg; t++) {
        int e = g_perm[beg + t];
        int c = __ldg(&cols[e]);
        float p = (t < MAXE) ? sp[w][t][hh]
                             : __expf(g_s[(size_t)e * 8 + hh] - m) * invz;
        const float* vr = g_qkv + (size_t)c * NQKV + 512;
        #pragma unroll
        for (int j = 0; j < 8; j++) acc[j] += p * vr[lane + 32 * j];
    }
    #pragma unroll
    for (int j = 0; j < 8; j++)
        g_of[frag_a16_idx(row, lane + 32 * j)] = __float2half_rn(acc[j]);
}

// ---------------- launch -----------------------------------------------------
extern "C" void kernel_launch(void* const* d_in, const int* in_sizes, int n_in,
                              void* d_out, int out_size)
{
    const float* h  = (const float*)d_in[0];
    const float* Wq = (const float*)d_in[1];
    const float* bq = (const float*)d_in[2];
    const float* Wk = (const float*)d_in[3];
    const float* bk = (const float*)d_in[4];
    const float* Wv = (const float*)d_in[5];
    const float* bv = (const float*)d_in[6];
    const float* Wo = (const float*)d_in[7];
    const float* bo = (const float*)d_in[8];
    const int* rows = (const int*)d_in[9];
    const int* cols = (const int*)d_in[10];
    float* out = (float*)d_out;

    void *paf, *pof, *pwf, *pbias, *pqkv, *pdeg, *pfill;
    cudaGetSymbolAddress(&paf, g_af);
    cudaGetSymbolAddress(&pof, g_of);
    cudaGetSymbolAddress(&pwf, g_wf);
    cudaGetSymbolAddress(&pbias, g_bias);
    cudaGetSymbolAddress(&pqkv, g_qkv);
    cudaGetSymbolAddress(&pdeg, g_deg);
    cudaGetSymbolAddress(&pfill, g_fill);
    __half* wf = (__half*)pwf;

    cudaFuncSetAttribute(gemm_mma, cudaFuncAttributeMaxDynamicSharedMemorySize, SMEM_GEMM);

    const float scaling = 0.17677669529663687f;  // 32^-0.5

    cudaMemsetAsync(pdeg, 0, NN * sizeof(int));
    cudaMemsetAsync(pfill, 0, NN * sizeof(int));

    // 1-3: prep
    prep_a<<<(NN * HID + 255) / 256, 256>>>(h);
    prep_wqkv<<<(3 * HID * HID + 255) / 256, 256>>>(Wq, Wk, Wv, bq, bk, bv);
    prep_wo<<<(HID * HID + 255) / 256, 256>>>(Wo);

    // 4: fused QKV GEMM (slot 4 for ncu)
    dim3 gQ((NN + 127) / 128, 3);
    gemm_mma<<<gQ, 256, SMEM_GEMM>>>((const __half*)paf, wf, (const float*)pbias,
                                     (float*)pqkv, NN, NQKV, scaling, 256);

    // 5-8: CSR build
    count_deg<<<(NE + 255) / 256, 256>>>(rows);
    scan_deg<<<1, 1024>>>();
    scatter_edges<<<(NE + 255) / 256, 256>>>(rows);
    sort_perm<<<(NN + 255) / 256, 256>>>();

    // 9: fused edge phase
    edge_fused<<<(NN + 7) / 8, 256>>>(cols);

    // 10: output GEMM
    dim3 gO((NN + 127) / 128, 1);
    gemm_mma<<<gO, 256, SMEM_GEMM>>>((const __half*)pof, wf + 196608, bo,
                                     out, NN, HID, 1.f, 0);
}